// round 13
// baseline (speedup 1.0000x reference)
#include <cuda_runtime.h>
#include <cstdint>

// ConditionalODE: fused MLP forward + exact 2-tangent JVP divergence.
// Round 13: 384 threads, 8row x 8col thread tiles (6 rowgroups x 64 colgroups).
// Lower CTA-wide B LDS traffic per fma-cycle + 170-reg budget enables explicit
// register prefetch of the 2nd kk4 half per panel (software pipelining).
// FFMA2 packed fp32; layer-0 cond@W0 hoisted per-batch (g_condW).

#define NTOK 131072
#define EPS  1e-5f

__device__ float g_condW[2048 * 512];   // per-batch cond @ W0[4:132]  (4 MB)

__device__ __forceinline__ void cp_async16(float* s, const float* g) {
    unsigned u = (unsigned)__cvta_generic_to_shared(s);
    asm volatile("cp.async.cg.shared.global [%0], [%1], 16;\n" :: "r"(u), "l"(g) : "memory");
}
__device__ __forceinline__ void cp_commit() {
    asm volatile("cp.async.commit_group;\n" ::: "memory");
}
__device__ __forceinline__ void cp_wait0() {
    asm volatile("cp.async.wait_group 0;\n" ::: "memory");
}
__device__ __forceinline__ void cp_wait1() {
    asm volatile("cp.async.wait_group 1;\n" ::: "memory");
}

// ---- packed fp32 helpers (sm_103a f32x2 pipe) ----
__device__ __forceinline__ unsigned long long splat2(float a) {
    unsigned long long r;
    unsigned ai = __float_as_uint(a);
    asm("mov.b64 %0, {%1, %1};" : "=l"(r) : "r"(ai));
    return r;
}
__device__ __forceinline__ void ffma2(unsigned long long& d,
                                      unsigned long long a, unsigned long long b) {
    asm("fma.rn.f32x2 %0, %1, %2, %0;" : "+l"(d) : "l"(a), "l"(b));
}

// GEMM: sOut[48][512] = sIn[48][512] @ Wb[512][512] using FFMA2.
// 384 threads: rg = tid>>6 (0..5) owns rows rg*8..rg*8+7 (warp-uniform ->
// A loads are LDS broadcasts); cg = tid&63 owns columns {cg*4..+3} and
// {256+cg*4..+3} as four f32x2 pairs per row.
// Weight k-panels (8x512) staged by threads 0..255 (64B each) via cp.async
// double buffer. Within a panel, the 2nd kk4 half's A/B regs are prefetched
// before the 1st half's FMA block.
__device__ __forceinline__ void gemm512(
    const float* __restrict__ Wb,
    const float* __restrict__ sIn, float* __restrict__ sW, float* __restrict__ sOut)
{
    const int tid = threadIdx.x;
    const int rg = tid >> 6;
    const int cg = tid & 63;
    const int rowBase = rg * 8;
    const int c0 = cg * 4;

    unsigned long long acc[8][4];
#pragma unroll
    for (int j = 0; j < 8; ++j)
#pragma unroll
        for (int m = 0; m < 4; ++m) acc[j][m] = 0ull;

    // staging: 256 threads x 64B (4 x cp16): row = t>>5 (0..7), col = (t&31)*16
    const int srow = (tid >> 5) & 7;
    const int scol = (tid & 31) * 16;
    const bool stager = (tid < 256);

    if (stager) {
#pragma unroll
        for (int q = 0; q < 4; ++q)
            cp_async16(sW + srow*512 + scol + q*4, Wb + srow*512 + scol + q*4);
    }
    cp_commit();

#pragma unroll 1
    for (int p = 0; p < 64; ++p) {
        float* cb = sW + (p & 1) * 4096;
        if (p + 1 < 64) {
            float* nb = sW + ((p + 1) & 1) * 4096;
            const float* src = Wb + (p + 1) * 4096;
            if (stager) {
#pragma unroll
                for (int q = 0; q < 4; ++q)
                    cp_async16(nb + srow*512 + scol + q*4, src + srow*512 + scol + q*4);
            }
            cp_commit();
            cp_wait1();
        } else {
            cp_wait0();
        }
        __syncthreads();

        const int kg = p << 3;
        // ---- load first kk4 half (k = kg..kg+3)
        float4 a0[8];
        ulonglong2 bA0[4], bB0[4];
#pragma unroll
        for (int j = 0; j < 8; ++j)
            a0[j] = *(const float4*)&sIn[(rowBase + j)*512 + kg];
#pragma unroll
        for (int kq = 0; kq < 4; ++kq) {
            bA0[kq] = *(const ulonglong2*)&cb[kq*512 + c0];
            bB0[kq] = *(const ulonglong2*)&cb[kq*512 + c0 + 256];
        }
        // ---- prefetch second kk4 half (k = kg+4..kg+7)
        float4 a1[8];
        ulonglong2 bA1[4], bB1[4];
#pragma unroll
        for (int j = 0; j < 8; ++j)
            a1[j] = *(const float4*)&sIn[(rowBase + j)*512 + kg + 4];
#pragma unroll
        for (int kq = 0; kq < 4; ++kq) {
            bA1[kq] = *(const ulonglong2*)&cb[(4 + kq)*512 + c0];
            bB1[kq] = *(const ulonglong2*)&cb[(4 + kq)*512 + c0 + 256];
        }
        // ---- compute first half
#pragma unroll
        for (int kq = 0; kq < 4; ++kq) {
#pragma unroll
            for (int j = 0; j < 8; ++j) {
                float av = (kq == 0) ? a0[j].x : (kq == 1) ? a0[j].y
                         : (kq == 2) ? a0[j].z : a0[j].w;
                unsigned long long a2 = splat2(av);
                ffma2(acc[j][0], a2, bA0[kq].x);
                ffma2(acc[j][1], a2, bA0[kq].y);
                ffma2(acc[j][2], a2, bB0[kq].x);
                ffma2(acc[j][3], a2, bB0[kq].y);
            }
        }
        // ---- compute second half
#pragma unroll
        for (int kq = 0; kq < 4; ++kq) {
#pragma unroll
            for (int j = 0; j < 8; ++j) {
                float av = (kq == 0) ? a1[j].x : (kq == 1) ? a1[j].y
                         : (kq == 2) ? a1[j].z : a1[j].w;
                unsigned long long a2 = splat2(av);
                ffma2(acc[j][0], a2, bA1[kq].x);
                ffma2(acc[j][1], a2, bA1[kq].y);
                ffma2(acc[j][2], a2, bB1[kq].x);
                ffma2(acc[j][3], a2, bB1[kq].y);
            }
        }
        __syncthreads();
    }
#pragma unroll
    for (int j = 0; j < 8; ++j) {
        *(ulonglong2*)&sOut[(rowBase + j)*512 + c0]       = make_ulonglong2(acc[j][0], acc[j][1]);
        *(ulonglong2*)&sOut[(rowBase + j)*512 + c0 + 256] = make_ulonglong2(acc[j][2], acc[j][3]);
    }
}

// Fused bias(te/pos) + LayerNorm + softplus, with JVP for two tangents.
// 12 warps; warp w handles tokens w, w+12 (strided). In-place on buf.
__device__ __forceinline__ void elementwise_ln(
    float* __restrict__ buf,
    const float* __restrict__ bvec, const float* __restrict__ gvec,
    const float* __restrict__ bevec, const float* __restrict__ Wfull,
    float tval, int tok0)
{
    const int wid = threadIdx.x >> 5;
    const int l = threadIdx.x & 31;
    for (int i = wid; i < 16; i += 12) {
        const float pos = (float)(((tok0 + i) & 63) + 1) * (1.f/64.f);
        float* xr  = buf + i*512;
        float* u0r = buf + (16+i)*512;
        float* u1r = buf + (32+i)*512;

        float s1=0.f,s2=0.f,s3=0.f,s4=0.f,s5=0.f,s6=0.f;
        for (int k = l; k < 512; k += 32) {
            float cv = __ldg(&bvec[k]) + tval*__ldg(&Wfull[k]) + pos*__ldg(&Wfull[512+k]);
            float x = xr[k] + cv;
            xr[k] = x;
            float u0 = u0r[k], u1 = u1r[k];
            s1 += x;     s2 += x*x;
            s3 += u0;    s4 += x*u0;
            s5 += u1;    s6 += x*u1;
        }
#pragma unroll
        for (int o = 16; o > 0; o >>= 1) {
            s1 += __shfl_xor_sync(0xffffffffu, s1, o);
            s2 += __shfl_xor_sync(0xffffffffu, s2, o);
            s3 += __shfl_xor_sync(0xffffffffu, s3, o);
            s4 += __shfl_xor_sync(0xffffffffu, s4, o);
            s5 += __shfl_xor_sync(0xffffffffu, s5, o);
            s6 += __shfl_xor_sync(0xffffffffu, s6, o);
        }
        const float inv = 1.f/512.f;
        float mu   = s1*inv;
        float var  = s2*inv - mu*mu;
        float r    = rsqrtf(var + EPS);
        float mu0  = s3*inv, mu1 = s5*inv;
        float cov0 = s4*inv - mu*mu0;
        float cov1 = s6*inv - mu*mu1;
        float r3c0 = r*r*r*cov0;
        float r3c1 = r*r*r*cov1;
        for (int k = l; k < 512; k += 32) {
            float x  = xr[k];
            float xc = x - mu;
            float gg = __ldg(&gvec[k]);
            float y  = fmaf(xc*r, gg, __ldg(&bevec[k]));
            float e  = __expf(-fabsf(y));
            float sp = fmaxf(y, 0.f) + log1pf(e);
            float sg = (y >= 0.f) ? (1.f/(1.f+e)) : (e/(1.f+e));
            float du0 = sg * gg * (r*(u0r[k]-mu0) - xc*r3c0);
            float du1 = sg * gg * (r*(u1r[k]-mu1) - xc*r3c1);
            xr[k]  = sp;
            u0r[k] = du0;
            u1r[k] = du1;
        }
    }
}

// Pre-kernel: g_condW[b][n] = sum_c cond[b][c] * W0[(4+c)*512+n].
__global__ void __launch_bounds__(512) condw_kernel(
    const float* __restrict__ cond, const float* __restrict__ W0)
{
    __shared__ float sc[8 * 128];
    const int n  = threadIdx.x;
    const int bb = blockIdx.x * 8;
    for (int idx = n; idx < 8*128; idx += 512) sc[idx] = cond[bb*128 + idx];
    __syncthreads();
    float acc[8];
#pragma unroll
    for (int j = 0; j < 8; ++j) acc[j] = 0.f;
    for (int c = 0; c < 128; ++c) {
        float w = W0[(4 + c)*512 + n];
#pragma unroll
        for (int j = 0; j < 8; ++j) acc[j] = fmaf(sc[j*128 + c], w, acc[j]);
    }
#pragma unroll
    for (int j = 0; j < 8; ++j) g_condW[(bb + j)*512 + n] = acc[j];
}

__global__ void __launch_bounds__(384, 1) ode_kernel(
    const float* __restrict__ tptr, const float* __restrict__ z,
    const float* __restrict__ cond,
    const float* __restrict__ W0, const float* __restrict__ b0,
    const float* __restrict__ g0, const float* __restrict__ be0,
    const float* __restrict__ W1, const float* __restrict__ b1,
    const float* __restrict__ g1, const float* __restrict__ be1,
    const float* __restrict__ W2, const float* __restrict__ b2,
    const float* __restrict__ g2, const float* __restrict__ be2,
    const float* __restrict__ W3, const float* __restrict__ b3,
    float* __restrict__ out)
{
    extern __shared__ float smem[];
    float* sA = smem;            // 48x512
    float* sB = smem + 24576;    // 48x512
    float* sW = smem + 49152;    // 2 x (8x512) weight panels
    const int tid  = threadIdx.x;
    const int tok0 = blockIdx.x * 16;
    const float tval = tptr[0];

    // ---- Layer 0 (algebraic): primal = z0*W0r2 + z1*W0r3 + condW; u0=W0r2, u1=W0r3
    if (tid < 32) sW[tid] = z[tok0*2 + tid];
    __syncthreads();
    for (int n = tid; n < 512; n += 384) {
        float w2  = W0[1024 + n];
        float w3  = W0[1536 + n];
        float cwv = g_condW[(tok0 >> 6)*512 + n];
#pragma unroll
        for (int i = 0; i < 16; ++i) {
            float z0 = sW[i*2], z1 = sW[i*2 + 1];
            sB[i*512 + n]        = fmaf(z0, w2, fmaf(z1, w3, cwv));
            sB[(16 + i)*512 + n] = w2;
            sB[(32 + i)*512 + n] = w3;
        }
    }
    __syncthreads();
    elementwise_ln(sB, b0, g0, be0, W0, tval, tok0);
    __syncthreads();

    // ---- Layer 1
    gemm512(W1 + 1024, sB, sW, sA);
    __syncthreads();
    elementwise_ln(sA, b1, g1, be1, W1, tval, tok0);
    __syncthreads();

    // ---- Layer 2
    gemm512(W2 + 1024, sA, sW, sB);
    __syncthreads();
    elementwise_ln(sB, b2, g2, be2, W2, tval, tok0);
    __syncthreads();

    // ---- Layer 3: per-token dots (warp per token, strided over 12 warps)
    {
        const int wid = tid >> 5, l = tid & 31;
        for (int i = wid; i < 16; i += 12) {
            const int token = tok0 + i;
            const float pos = (float)((token & 63) + 1) * (1.f/64.f);
            const float* xr  = sB + i*512;
            const float* u0r = sB + (16+i)*512;
            const float* u1r = sB + (32+i)*512;
            float a0=0.f, a1=0.f, d0=0.f, d1=0.f;
            for (int k = l; k < 512; k += 32) {
                float2 wv = *(const float2*)&W3[(2+k)*2];
                float h = xr[k];
                a0 = fmaf(h, wv.x, a0);
                a1 = fmaf(h, wv.y, a1);
                d0 = fmaf(u0r[k], wv.x, d0);
                d1 = fmaf(u1r[k], wv.y, d1);
            }
#pragma unroll
            for (int o = 16; o > 0; o >>= 1) {
                a0 += __shfl_xor_sync(0xffffffffu, a0, o);
                a1 += __shfl_xor_sync(0xffffffffu, a1, o);
                d0 += __shfl_xor_sync(0xffffffffu, d0, o);
                d1 += __shfl_xor_sync(0xffffffffu, d1, o);
            }
            if (l == 0) {
                out[token*2 + 0] = a0 + b3[0] + tval*W3[0] + pos*W3[2];
                out[token*2 + 1] = a1 + b3[1] + tval*W3[1] + pos*W3[3];
                out[2*NTOK + token] = -(d0 + d1);
            }
        }
    }
}

extern "C" void kernel_launch(void* const* d_in, const int* in_sizes, int n_in,
                              void* d_out, int out_size)
{
    const float* t    = (const float*)d_in[0];
    const float* z    = (const float*)d_in[1];
    const float* cond = (const float*)d_in[2];
    const float* W0   = (const float*)d_in[3];
    const float* b0   = (const float*)d_in[4];
    const float* g0   = (const float*)d_in[5];
    const float* be0  = (const float*)d_in[6];
    const float* W1   = (const float*)d_in[7];
    const float* b1   = (const float*)d_in[8];
    const float* g1   = (const float*)d_in[9];
    const float* be1  = (const float*)d_in[10];
    const float* W2   = (const float*)d_in[11];
    const float* b2   = (const float*)d_in[12];
    const float* g2   = (const float*)d_in[13];
    const float* be2  = (const float*)d_in[14];
    const float* W3   = (const float*)d_in[15];
    const float* b3   = (const float*)d_in[16];
    float* out = (float*)d_out;

    condw_kernel<<<256, 512>>>(cond, W0);

    const size_t smem_bytes = 57344 * sizeof(float);  // 229376 B
    cudaFuncSetAttribute(ode_kernel, cudaFuncAttributeMaxDynamicSharedMemorySize,
                         (int)smem_bytes);
    ode_kernel<<<NTOK/16, 384, smem_bytes>>>(
        t, z, cond, W0, b0, g0, be0, W1, b1, g1, be1,
        W2, b2, g2, be2, W3, b3, out);
}

// round 14
// speedup vs baseline: 1.1415x; 1.1415x over previous
#include <cuda_runtime.h>
#include <cstdint>

// ConditionalODE: fused MLP forward + exact 2-tangent JVP divergence.
// Round 14: back to 512-thread config (R10 winner) with
//  (a) 4 rowgroups x 12 rows, 4 cols/thread tile -> B LDS redundancy 8x->4x,
//      crossbar demand (~1200 cyc/panel) drops below fma floor (~1460);
//  (b) ONE __syncthreads per weight panel: cp.async(p+1) issued AFTER the
//      barrier (target buffer held p-1, readers proven done), trailing
//      barrier removed -> warps desync within panel, LDS overlaps FFMA2.
// FFMA2 packed fp32; layer-0 cond@W0 hoisted per-batch (g_condW).

#define NTOK 131072
#define EPS  1e-5f

__device__ float g_condW[2048 * 512];   // per-batch cond @ W0[4:132]  (4 MB)

__device__ __forceinline__ void cp_async16(float* s, const float* g) {
    unsigned u = (unsigned)__cvta_generic_to_shared(s);
    asm volatile("cp.async.cg.shared.global [%0], [%1], 16;\n" :: "r"(u), "l"(g) : "memory");
}
__device__ __forceinline__ void cp_commit() {
    asm volatile("cp.async.commit_group;\n" ::: "memory");
}
__device__ __forceinline__ void cp_wait0() {
    asm volatile("cp.async.wait_group 0;\n" ::: "memory");
}

// ---- packed fp32 helpers (sm_103a f32x2 pipe) ----
__device__ __forceinline__ unsigned long long splat2(float a) {
    unsigned long long r;
    unsigned ai = __float_as_uint(a);
    asm("mov.b64 %0, {%1, %1};" : "=l"(r) : "r"(ai));
    return r;
}
__device__ __forceinline__ void ffma2(unsigned long long& d,
                                      unsigned long long a, unsigned long long b) {
    asm("fma.rn.f32x2 %0, %1, %2, %0;" : "+l"(d) : "l"(a), "l"(b));
}

// GEMM: sOut[48][512] = sIn[48][512] @ Wb[512][512] using FFMA2.
// 512 threads: rg = tid>>7 (0..3) owns rows rg*12..rg*12+11 (warp-uniform ->
// A loads are LDS broadcasts); cg = tid&127 owns columns cg*4..cg*4+3 as two
// f32x2 pairs per row. B loads: one ulonglong2 (16B, lane-consecutive) per kq.
// Weight k-panels (8x512) double-buffered via cp.async; ONE barrier per panel.
__device__ __forceinline__ void gemm512(
    const float* __restrict__ Wb,
    const float* __restrict__ sIn, float* __restrict__ sW, float* __restrict__ sOut)
{
    const int tid = threadIdx.x;
    const int rowBase = (tid >> 7) * 12;
    const int c0 = (tid & 127) * 4;

    unsigned long long acc[12][2];
#pragma unroll
    for (int j = 0; j < 12; ++j) { acc[j][0] = 0ull; acc[j][1] = 0ull; }

    // staging: 512 threads x 32B: row = tid>>6 (0..7), col = (tid&63)*8
    const int srow = tid >> 6;
    const int scol = (tid & 63) * 8;

    // prologue: stage panel 0 into buffer 0
    cp_async16(sW + srow*512 + scol,     Wb + srow*512 + scol);
    cp_async16(sW + srow*512 + scol + 4, Wb + srow*512 + scol + 4);
    cp_commit();

#pragma unroll 1
    for (int p = 0; p < 64; ++p) {
        float* cb = sW + (p & 1) * 4096;
        cp_wait0();          // own parts of panel p done
        __syncthreads();     // all parts of p visible; readers of p-1 done
        if (p + 1 < 64) {
            // buffer (p+1)&1 held panel p-1: safe to overwrite now
            float* nb = sW + ((p + 1) & 1) * 4096;
            const float* src = Wb + (p + 1) * 4096;
            cp_async16(nb + srow*512 + scol,     src + srow*512 + scol);
            cp_async16(nb + srow*512 + scol + 4, src + srow*512 + scol + 4);
            cp_commit();
        }
#pragma unroll
        for (int kk = 0; kk < 8; kk += 4) {
            const int kg = (p << 3) + kk;
            float4 a[12];
#pragma unroll
            for (int j = 0; j < 12; ++j)
                a[j] = *(const float4*)&sIn[(rowBase + j)*512 + kg];
#pragma unroll
            for (int kq = 0; kq < 4; ++kq) {
                ulonglong2 bv = *(const ulonglong2*)&cb[(kk + kq)*512 + c0];
#pragma unroll
                for (int j = 0; j < 12; ++j) {
                    float av = (kq == 0) ? a[j].x : (kq == 1) ? a[j].y
                             : (kq == 2) ? a[j].z : a[j].w;
                    unsigned long long a2 = splat2(av);
                    ffma2(acc[j][0], a2, bv.x);
                    ffma2(acc[j][1], a2, bv.y);
                }
            }
        }
        // no trailing barrier: next iteration's top barrier gates reuse
    }
#pragma unroll
    for (int j = 0; j < 12; ++j)
        *(ulonglong2*)&sOut[(rowBase + j)*512 + c0] = make_ulonglong2(acc[j][0], acc[j][1]);
}

// Fused bias(te/pos) + LayerNorm + softplus, with JVP for two tangents.
// One warp per token (16 warps). In-place on buf.
__device__ __forceinline__ void elementwise_ln(
    float* __restrict__ buf,
    const float* __restrict__ bvec, const float* __restrict__ gvec,
    const float* __restrict__ bevec, const float* __restrict__ Wfull,
    float tval, int tok0)
{
    const int i = threadIdx.x >> 5;
    const int l = threadIdx.x & 31;
    const float pos = (float)(((tok0 + i) & 63) + 1) * (1.f/64.f);
    float* xr  = buf + i*512;
    float* u0r = buf + (16+i)*512;
    float* u1r = buf + (32+i)*512;

    float s1=0.f,s2=0.f,s3=0.f,s4=0.f,s5=0.f,s6=0.f;
    for (int k = l; k < 512; k += 32) {
        float cv = __ldg(&bvec[k]) + tval*__ldg(&Wfull[k]) + pos*__ldg(&Wfull[512+k]);
        float x = xr[k] + cv;
        xr[k] = x;
        float u0 = u0r[k], u1 = u1r[k];
        s1 += x;     s2 += x*x;
        s3 += u0;    s4 += x*u0;
        s5 += u1;    s6 += x*u1;
    }
#pragma unroll
    for (int o = 16; o > 0; o >>= 1) {
        s1 += __shfl_xor_sync(0xffffffffu, s1, o);
        s2 += __shfl_xor_sync(0xffffffffu, s2, o);
        s3 += __shfl_xor_sync(0xffffffffu, s3, o);
        s4 += __shfl_xor_sync(0xffffffffu, s4, o);
        s5 += __shfl_xor_sync(0xffffffffu, s5, o);
        s6 += __shfl_xor_sync(0xffffffffu, s6, o);
    }
    const float inv = 1.f/512.f;
    float mu   = s1*inv;
    float var  = s2*inv - mu*mu;
    float r    = rsqrtf(var + EPS);
    float mu0  = s3*inv, mu1 = s5*inv;
    float cov0 = s4*inv - mu*mu0;
    float cov1 = s6*inv - mu*mu1;
    float r3c0 = r*r*r*cov0;
    float r3c1 = r*r*r*cov1;
    for (int k = l; k < 512; k += 32) {
        float x  = xr[k];
        float xc = x - mu;
        float gg = __ldg(&gvec[k]);
        float y  = fmaf(xc*r, gg, __ldg(&bevec[k]));
        float e  = __expf(-fabsf(y));
        float sp = fmaxf(y, 0.f) + log1pf(e);
        float sg = (y >= 0.f) ? (1.f/(1.f+e)) : (e/(1.f+e));
        float du0 = sg * gg * (r*(u0r[k]-mu0) - xc*r3c0);
        float du1 = sg * gg * (r*(u1r[k]-mu1) - xc*r3c1);
        xr[k]  = sp;
        u0r[k] = du0;
        u1r[k] = du1;
    }
}

// Pre-kernel: g_condW[b][n] = sum_c cond[b][c] * W0[(4+c)*512+n].
__global__ void __launch_bounds__(512) condw_kernel(
    const float* __restrict__ cond, const float* __restrict__ W0)
{
    __shared__ float sc[8 * 128];
    const int n  = threadIdx.x;
    const int bb = blockIdx.x * 8;
    for (int idx = n; idx < 8*128; idx += 512) sc[idx] = cond[bb*128 + idx];
    __syncthreads();
    float acc[8];
#pragma unroll
    for (int j = 0; j < 8; ++j) acc[j] = 0.f;
    for (int c = 0; c < 128; ++c) {
        float w = W0[(4 + c)*512 + n];
#pragma unroll
        for (int j = 0; j < 8; ++j) acc[j] = fmaf(sc[j*128 + c], w, acc[j]);
    }
#pragma unroll
    for (int j = 0; j < 8; ++j) g_condW[(bb + j)*512 + n] = acc[j];
}

__global__ void __launch_bounds__(512, 1) ode_kernel(
    const float* __restrict__ tptr, const float* __restrict__ z,
    const float* __restrict__ cond,
    const float* __restrict__ W0, const float* __restrict__ b0,
    const float* __restrict__ g0, const float* __restrict__ be0,
    const float* __restrict__ W1, const float* __restrict__ b1,
    const float* __restrict__ g1, const float* __restrict__ be1,
    const float* __restrict__ W2, const float* __restrict__ b2,
    const float* __restrict__ g2, const float* __restrict__ be2,
    const float* __restrict__ W3, const float* __restrict__ b3,
    float* __restrict__ out)
{
    extern __shared__ float smem[];
    float* sA = smem;            // 48x512
    float* sB = smem + 24576;    // 48x512
    float* sW = smem + 49152;    // 2 x (8x512) weight panels
    const int tid  = threadIdx.x;
    const int tok0 = blockIdx.x * 16;
    const float tval = tptr[0];

    // ---- Layer 0 (algebraic): primal = z0*W0r2 + z1*W0r3 + condW; u0=W0r2, u1=W0r3
    if (tid < 32) sW[tid] = z[tok0*2 + tid];
    __syncthreads();
    {
        const int n = tid;
        float w2  = W0[1024 + n];
        float w3  = W0[1536 + n];
        float cwv = g_condW[(tok0 >> 6)*512 + n];
#pragma unroll
        for (int i = 0; i < 16; ++i) {
            float z0 = sW[i*2], z1 = sW[i*2 + 1];
            sB[i*512 + n]        = fmaf(z0, w2, fmaf(z1, w3, cwv));
            sB[(16 + i)*512 + n] = w2;
            sB[(32 + i)*512 + n] = w3;
        }
    }
    __syncthreads();
    elementwise_ln(sB, b0, g0, be0, W0, tval, tok0);
    __syncthreads();

    // ---- Layer 1
    gemm512(W1 + 1024, sB, sW, sA);
    __syncthreads();
    elementwise_ln(sA, b1, g1, be1, W1, tval, tok0);
    __syncthreads();

    // ---- Layer 2
    gemm512(W2 + 1024, sA, sW, sB);
    __syncthreads();
    elementwise_ln(sB, b2, g2, be2, W2, tval, tok0);
    __syncthreads();

    // ---- Layer 3: per-token dots (warp per token)
    {
        const int i = tid >> 5, l = tid & 31;
        const int token = tok0 + i;
        const float pos = (float)((token & 63) + 1) * (1.f/64.f);
        const float* xr  = sB + i*512;
        const float* u0r = sB + (16+i)*512;
        const float* u1r = sB + (32+i)*512;
        float a0=0.f, a1=0.f, d0=0.f, d1=0.f;
        for (int k = l; k < 512; k += 32) {
            float2 wv = *(const float2*)&W3[(2+k)*2];
            float h = xr[k];
            a0 = fmaf(h, wv.x, a0);
            a1 = fmaf(h, wv.y, a1);
            d0 = fmaf(u0r[k], wv.x, d0);
            d1 = fmaf(u1r[k], wv.y, d1);
        }
#pragma unroll
        for (int o = 16; o > 0; o >>= 1) {
            a0 += __shfl_xor_sync(0xffffffffu, a0, o);
            a1 += __shfl_xor_sync(0xffffffffu, a1, o);
            d0 += __shfl_xor_sync(0xffffffffu, d0, o);
            d1 += __shfl_xor_sync(0xffffffffu, d1, o);
        }
        if (l == 0) {
            out[token*2 + 0] = a0 + b3[0] + tval*W3[0] + pos*W3[2];
            out[token*2 + 1] = a1 + b3[1] + tval*W3[1] + pos*W3[3];
            out[2*NTOK + token] = -(d0 + d1);
        }
    }
}

extern "C" void kernel_launch(void* const* d_in, const int* in_sizes, int n_in,
                              void* d_out, int out_size)
{
    const float* t    = (const float*)d_in[0];
    const float* z    = (const float*)d_in[1];
    const float* cond = (const float*)d_in[2];
    const float* W0   = (const float*)d_in[3];
    const float* b0   = (const float*)d_in[4];
    const float* g0   = (const float*)d_in[5];
    const float* be0  = (const float*)d_in[6];
    const float* W1   = (const float*)d_in[7];
    const float* b1   = (const float*)d_in[8];
    const float* g1   = (const float*)d_in[9];
    const float* be1  = (const float*)d_in[10];
    const float* W2   = (const float*)d_in[11];
    const float* b2   = (const float*)d_in[12];
    const float* g2   = (const float*)d_in[13];
    const float* be2  = (const float*)d_in[14];
    const float* W3   = (const float*)d_in[15];
    const float* b3   = (const float*)d_in[16];
    float* out = (float*)d_out;

    condw_kernel<<<256, 512>>>(cond, W0);

    const size_t smem_bytes = 57344 * sizeof(float);  // 229376 B
    cudaFuncSetAttribute(ode_kernel, cudaFuncAttributeMaxDynamicSharedMemorySize,
                         (int)smem_bytes);
    ode_kernel<<<NTOK/16, 512, smem_bytes>>>(
        t, z, cond, W0, b0, g0, be0, W1, b1, g1, be1,
        W2, b2, g2, be2, W3, b3, out);
}